// round 6
// baseline (speedup 1.0000x reference)
#include <cuda_runtime.h>

typedef unsigned long long u64;

#define HID 128
#define NA  1024
#define NR  1024

// Scratch: PA (bs1 folded in) and PR, row-major [row][h]
__device__ float g_PA[NA * HID];
__device__ float g_PR[NR * HID];

// ---------------- packed f32x2 helpers (sm_103a FADD2/FFMA2) ----------------
__device__ __forceinline__ u64 dup2(float v) {
    u64 d; asm("mov.b64 %0,{%1,%1};" : "=l"(d) : "f"(v)); return d;
}
__device__ __forceinline__ u64 pack2(float lo, float hi) {
    u64 d; asm("mov.b64 %0,{%1,%2};" : "=l"(d) : "f"(lo), "f"(hi)); return d;
}
__device__ __forceinline__ float2 unpack2(u64 d) {
    float2 r; asm("mov.b64 {%0,%1},%2;" : "=f"(r.x), "=f"(r.y) : "l"(d)); return r;
}
__device__ __forceinline__ u64 fadd2_(u64 a, u64 b) {
    u64 d; asm("add.rn.f32x2 %0,%1,%2;" : "=l"(d) : "l"(a), "l"(b)); return d;
}
__device__ __forceinline__ u64 ffma2_(u64 a, u64 b, u64 c) {
    u64 d; asm("fma.rn.f32x2 %0,%1,%2,%3;" : "=l"(d) : "l"(a), "l"(b), "l"(c)); return d;
}
__device__ __forceinline__ u64 relu2_(u64 x) {
    u64 d;
    asm("{\n\t.reg .f32 lo,hi;\n\t"
        "mov.b64 {lo,hi},%1;\n\t"
        "max.f32 lo,lo,0f00000000;\n\t"
        "max.f32 hi,hi,0f00000000;\n\t"
        "mov.b64 %0,{lo,hi};\n\t}"
        : "=l"(d) : "l"(x));
    return d;
}
// acc += relu(a2 + r2) * w2   (2 h-lanes packed)
__device__ __forceinline__ u64 addrelufma(u64 acc, u64 a2, u64 r2, u64 w2) {
    asm("{\n\t.reg .b64 t;\n\t.reg .f32 lo,hi;\n\t"
        "add.rn.f32x2 t,%1,%2;\n\t"
        "mov.b64 {lo,hi},t;\n\t"
        "max.f32 lo,lo,0f00000000;\n\t"
        "max.f32 hi,hi,0f00000000;\n\t"
        "mov.b64 t,{lo,hi};\n\t"
        "fma.rn.f32x2 %0,t,%3,%0;\n\t}"
        : "+l"(acc) : "l"(a2), "l"(r2), "l"(w2));
    return acc;
}

// ---------------------------------------------------------------------------
// 128x128 MLP layer pass, f32x2 row-pairs (2 pairs per thread-half),
// 8-deep register prefetch of the weight column.
// ---------------------------------------------------------------------------
__device__ __forceinline__ void mlp128_2(const float* __restrict__ Wp, int j, int pb,
                                         const u64 (*__restrict__ hT)[4], u64 acc[2])
{
    acc[0] = acc[1] = 0ull;
    float wA[8], wB[8];
    #pragma unroll
    for (int i = 0; i < 8; ++i) wA[i] = Wp[i * HID + j];
    #pragma unroll 1
    for (int kb = 0; kb < 128; kb += 16) {
        #pragma unroll
        for (int i = 0; i < 8; ++i) wB[i] = Wp[(kb + 8 + i) * HID + j];
        #pragma unroll
        for (int i = 0; i < 8; ++i) {
            int k = kb + i;
            u64 w2 = dup2(wA[i]);
            ulonglong2 x01 = *(const ulonglong2*)&hT[k][pb];
            acc[0] = ffma2_(x01.x, w2, acc[0]);
            acc[1] = ffma2_(x01.y, w2, acc[1]);
        }
        #pragma unroll
        for (int i = 0; i < 8; ++i)
            wA[i] = (kb + 16 + i < 128) ? Wp[(kb + 16 + i) * HID + j] : 0.f;
        #pragma unroll
        for (int i = 0; i < 8; ++i) {
            int k = kb + 8 + i;
            u64 w2 = dup2(wB[i]);
            ulonglong2 x01 = *(const ulonglong2*)&hT[k][pb];
            acc[0] = ffma2_(x01.x, w2, acc[0]);
            acc[1] = ffma2_(x01.y, w2, acc[1]);
        }
    }
}

// ---------------------------------------------------------------------------
// Kernel 1: fused MLP chain. 256 blocks (128 agent + 128 region) x 256
// threads, 8 rows per block. j = t&127 (column); half = t>>7 owns 2 row-pairs.
// ---------------------------------------------------------------------------
__global__ __launch_bounds__(256) void embed_kernel(
    const float* __restrict__ xa,  const float* __restrict__ xr,
    const float* __restrict__ Wa1, const float* __restrict__ ba1,
    const float* __restrict__ Wa2, const float* __restrict__ ba2,
    const float* __restrict__ Wr1, const float* __restrict__ br1,
    const float* __restrict__ Wr2, const float* __restrict__ br2,
    const float* __restrict__ Ws1, const float* __restrict__ bs1)
{
    const int ROWS = 8;
    int blk = blockIdx.x;
    bool agent = blk < 128;
    int rbase = (agent ? blk : blk - 128) * ROWS;
    int idim = agent ? 24 : 20;
    const float* x  = agent ? (xa + rbase * 24) : (xr + rbase * 20);
    const float* W1 = agent ? Wa1 : Wr1;
    const float* b1 = agent ? ba1 : br1;
    const float* W2 = agent ? Wa2 : Wr2;
    const float* b2 = agent ? ba2 : br2;
    const float* Ws = agent ? Ws1 : (Ws1 + HID * HID);
    float* outp = agent ? g_PA : g_PR;

    __shared__ __align__(16) u64 xsp[24][4];   // packed input [k][row-pair]
    __shared__ __align__(16) u64 hT[HID][4];   // packed activ [k][row-pair]

    int t = threadIdx.x;
    int j = t & 127;
    int pb = (t >> 7) * 2;     // row-pair base (0 or 2)

    // Stage packed input rows
    if (t < idim * 4) {
        int k = t >> 2, p = t & 3;
        xsp[k][p] = pack2(x[(2 * p) * idim + k], x[(2 * p + 1) * idim + k]);
    }
    __syncthreads();

    // Layer 1
    u64 acc[2];
    {
        u64 bp = dup2(b1[j]);
        acc[0] = acc[1] = bp;
        #pragma unroll 4
        for (int k = 0; k < idim; ++k) {
            u64 w2 = dup2(W1[k * HID + j]);
            ulonglong2 x01 = *(const ulonglong2*)&xsp[k][pb];
            acc[0] = ffma2_(x01.x, w2, acc[0]);
            acc[1] = ffma2_(x01.y, w2, acc[1]);
        }
        hT[j][pb]     = relu2_(acc[0]);
        hT[j][pb + 1] = relu2_(acc[1]);
    }
    __syncthreads();

    // Layer 2
    mlp128_2(W2, j, pb, hT, acc);
    {
        u64 b2d = dup2(b2[j]);
        __syncthreads();             // all hT reads done before overwrite
        hT[j][pb]     = relu2_(fadd2_(acc[0], b2d));
        hT[j][pb + 1] = relu2_(fadd2_(acc[1], b2d));
    }
    __syncthreads();

    // Score projection
    mlp128_2(Ws, j, pb, hT, acc);
    u64 bsd = agent ? dup2(bs1[j]) : 0ull;
    #pragma unroll
    for (int p = 0; p < 2; ++p) {
        u64 v = agent ? fadd2_(acc[p], bsd) : acc[p];
        float2 f = unpack2(v);
        int row = rbase + 2 * (pb + p);
        outp[row * HID + j]       = f.x;
        outp[(row + 1) * HID + j] = f.y;
    }
}

// ---------------------------------------------------------------------------
// Kernel 2: pairwise scores, f32x2 packed over (h, h+1).
// Tile 32a x 32r, 128 threads, 2a x 4r per thread (a = ty+16i, r = tx+8jj).
// Grid 1024 blocks -> ~7 blocks/SM, near-perfect wave balance.
// launch_bounds(128,8): <=64 regs -> 8 blocks/SM (50% occ).
// Pitch 68 floats (16B-aligned rows; conflict-free LDS.64 / STS.128).
// h in 2 chunks of 64; accumulators packed over h-lanes, horizontal add once.
// ---------------------------------------------------------------------------
__global__ __launch_bounds__(128, 8) void pair_kernel(
    const float* __restrict__ Ws2, const float* __restrict__ bs2,
    float* __restrict__ out)
{
    __shared__ __align__(16) float As[32 * 68];   // [a][h_local], pitch 68
    __shared__ __align__(16) float Rs[32 * 68];   // [r][h_local]
    __shared__ __align__(16) u64   wsp[64];       // Ws2 as natural h-pairs

    int t  = threadIdx.x;
    int tx = t & 7;          // r = tx + 8*jj
    int ty = t >> 3;         // a = ty + 16*i
    int a0 = blockIdx.y * 32;
    int r0 = blockIdx.x * 32;

    if (t < 64) wsp[t] = ((const u64*)Ws2)[t];

    u64 acc[2][4];
    #pragma unroll
    for (int i = 0; i < 2; ++i)
        #pragma unroll
        for (int jj = 0; jj < 4; ++jj) acc[i][jj] = 0ull;

    const u64* As64 = (const u64*)As;   // pitch 34 u64
    const u64* Rs64 = (const u64*)Rs;

    for (int c = 0; c < 2; ++c) {
        int hb = 64 * c;
        __syncthreads();   // previous chunk's reads done (and wsp on c==0)

        #pragma unroll
        for (int it = 0; it < 4; ++it) {
            int idx = t + 128 * it;
            int row = idx >> 4, c4 = idx & 15;
            *(float4*)&As[row * 68 + 4 * c4] =
                *(const float4*)&g_PA[(size_t)(a0 + row) * HID + hb + 4 * c4];
            *(float4*)&Rs[row * 68 + 4 * c4] =
                *(const float4*)&g_PR[(size_t)(r0 + row) * HID + hb + 4 * c4];
        }
        __syncthreads();

        #pragma unroll 4
        for (int hp = 0; hp < 32; ++hp) {   // one packed h-pair per iter
            u64 w2  = wsp[32 * c + hp];
            u64 av0 = As64[ty * 34 + hp];
            u64 av1 = As64[(ty + 16) * 34 + hp];
            u64 rv0 = Rs64[tx * 34 + hp];
            u64 rv1 = Rs64[(tx + 8) * 34 + hp];
            u64 rv2 = Rs64[(tx + 16) * 34 + hp];
            u64 rv3 = Rs64[(tx + 24) * 34 + hp];
            acc[0][0] = addrelufma(acc[0][0], av0, rv0, w2);
            acc[0][1] = addrelufma(acc[0][1], av0, rv1, w2);
            acc[0][2] = addrelufma(acc[0][2], av0, rv2, w2);
            acc[0][3] = addrelufma(acc[0][3], av0, rv3, w2);
            acc[1][0] = addrelufma(acc[1][0], av1, rv0, w2);
            acc[1][1] = addrelufma(acc[1][1], av1, rv1, w2);
            acc[1][2] = addrelufma(acc[1][2], av1, rv2, w2);
            acc[1][3] = addrelufma(acc[1][3], av1, rv3, w2);
        }
    }

    float b = *bs2;
    #pragma unroll
    for (int i = 0; i < 2; ++i) {
        int a = a0 + ty + 16 * i;
        #pragma unroll
        for (int jj = 0; jj < 4; ++jj) {
            float2 p = unpack2(acc[i][jj]);
            out[(size_t)a * NR + r0 + tx + 8 * jj] = (p.x + p.y) + b;
        }
    }
}

// ---------------------------------------------------------------------------
extern "C" void kernel_launch(void* const* d_in, const int* in_sizes, int n_in,
                              void* d_out, int out_size)
{
    const float* xa  = (const float*)d_in[0];
    const float* xr  = (const float*)d_in[1];
    const float* Wa1 = (const float*)d_in[2];
    const float* ba1 = (const float*)d_in[3];
    const float* Wa2 = (const float*)d_in[4];
    const float* ba2 = (const float*)d_in[5];
    const float* Wr1 = (const float*)d_in[6];
    const float* br1 = (const float*)d_in[7];
    const float* Wr2 = (const float*)d_in[8];
    const float* br2 = (const float*)d_in[9];
    const float* Ws1 = (const float*)d_in[10];
    const float* bs1 = (const float*)d_in[11];
    const float* Ws2 = (const float*)d_in[12];
    const float* bs2 = (const float*)d_in[13];
    float* out = (float*)d_out;

    embed_kernel<<<256, 256>>>(xa, xr, Wa1, ba1, Wa2, ba2,
                               Wr1, br1, Wr2, br2, Ws1, bs1);
    pair_kernel<<<dim3(NR / 32, NA / 32), 128>>>(Ws2, bs2, out);
}

// round 7
// speedup vs baseline: 1.0648x; 1.0648x over previous
#include <cuda_runtime.h>

typedef unsigned long long u64;

#define HID 128
#define NA  1024
#define NR  1024

// Scratch: PA (bs1 folded in) and PR, row-major [row][h]
__device__ float g_PA[NA * HID];
__device__ float g_PR[NR * HID];

// ---------------- packed f32x2 helpers (sm_103a FADD2/FFMA2) ----------------
__device__ __forceinline__ u64 dup2(float v) {
    u64 d; asm("mov.b64 %0,{%1,%1};" : "=l"(d) : "f"(v)); return d;
}
__device__ __forceinline__ u64 pack2(float lo, float hi) {
    u64 d; asm("mov.b64 %0,{%1,%2};" : "=l"(d) : "f"(lo), "f"(hi)); return d;
}
__device__ __forceinline__ float2 unpack2(u64 d) {
    float2 r; asm("mov.b64 {%0,%1},%2;" : "=f"(r.x), "=f"(r.y) : "l"(d)); return r;
}
__device__ __forceinline__ u64 fadd2_(u64 a, u64 b) {
    u64 d; asm("add.rn.f32x2 %0,%1,%2;" : "=l"(d) : "l"(a), "l"(b)); return d;
}
__device__ __forceinline__ u64 ffma2_(u64 a, u64 b, u64 c) {
    u64 d; asm("fma.rn.f32x2 %0,%1,%2,%3;" : "=l"(d) : "l"(a), "l"(b), "l"(c)); return d;
}
__device__ __forceinline__ u64 relu2_(u64 x) {
    u64 d;
    asm("{\n\t.reg .f32 lo,hi;\n\t"
        "mov.b64 {lo,hi},%1;\n\t"
        "max.f32 lo,lo,0f00000000;\n\t"
        "max.f32 hi,hi,0f00000000;\n\t"
        "mov.b64 %0,{lo,hi};\n\t}"
        : "=l"(d) : "l"(x));
    return d;
}
// acc += relu(a2 + r2) * w2   (2 h-lanes packed)
__device__ __forceinline__ u64 addrelufma(u64 acc, u64 a2, u64 r2, u64 w2) {
    asm("{\n\t.reg .b64 t;\n\t.reg .f32 lo,hi;\n\t"
        "add.rn.f32x2 t,%1,%2;\n\t"
        "mov.b64 {lo,hi},t;\n\t"
        "max.f32 lo,lo,0f00000000;\n\t"
        "max.f32 hi,hi,0f00000000;\n\t"
        "mov.b64 t,{lo,hi};\n\t"
        "fma.rn.f32x2 %0,t,%3,%0;\n\t}"
        : "+l"(acc) : "l"(a2), "l"(r2), "l"(w2));
    return acc;
}

// ---------------- cp.async helpers ----------------
__device__ __forceinline__ void cp_async16(unsigned saddr, const void* g) {
    asm volatile("cp.async.cg.shared.global [%0], [%1], 16;" :: "r"(saddr), "l"(g));
}
__device__ __forceinline__ void cp_commit() { asm volatile("cp.async.commit_group;"); }
__device__ __forceinline__ void cp_wait0()  { asm volatile("cp.async.wait_group 0;" ::: "memory"); }

// ---------------------------------------------------------------------------
// Kernel 1: fused MLP chain. 128 blocks (64 agent + 64 region) x 128 threads,
// 16 rows per block, thread t = column t (owns all 8 row-pairs).
// W2/Ws streamed via cp.async double buffer (32-k chunks), prefetch overlapped
// with compute of the previous chunk. Inner loop is LDS+FFMA2 only.
// ---------------------------------------------------------------------------
#define CHK 32    // k per chunk
__global__ __launch_bounds__(128) void embed_kernel(
    const float* __restrict__ xa,  const float* __restrict__ xr,
    const float* __restrict__ Wa1, const float* __restrict__ ba1,
    const float* __restrict__ Wa2, const float* __restrict__ ba2,
    const float* __restrict__ Wr1, const float* __restrict__ br1,
    const float* __restrict__ Wr2, const float* __restrict__ br2,
    const float* __restrict__ Ws1, const float* __restrict__ bs1)
{
    const int ROWS = 16;
    int blk = blockIdx.x;
    bool agent = blk < 64;
    int rbase = (agent ? blk : blk - 64) * ROWS;
    int idim = agent ? 24 : 20;
    const float* x  = agent ? (xa + rbase * 24) : (xr + rbase * 20);
    const float* W1 = agent ? Wa1 : Wr1;
    const float* b1 = agent ? ba1 : br1;
    const float* W2 = agent ? Wa2 : Wr2;
    const float* b2 = agent ? ba2 : br2;
    const float* Ws = agent ? Ws1 : (Ws1 + HID * HID);
    float* outp = agent ? g_PA : g_PR;

    __shared__ __align__(16) u64 xp[24][8];            // packed input [k][pair]
    __shared__ __align__(16) u64 hT[HID][8];           // packed activ [k][pair]
    __shared__ __align__(16) float Wbuf[2][CHK * HID]; // 2 x 16KB

    int t = threadIdx.x;   // column j = t

    // Prefetch chunk 0 (W2 k=0..31) into buf 0
    {
        unsigned s = (unsigned)__cvta_generic_to_shared(&Wbuf[0][0]);
        #pragma unroll
        for (int i = 0; i < 8; ++i) {
            int seg = i * 128 + t;
            cp_async16(s + seg * 16, W2 + seg * 4);
        }
        cp_commit();
    }

    // Stage packed input rows
    for (int i = t; i < idim * 8; i += 128) {
        int k = i >> 3, p = i & 7;
        xp[k][p] = pack2(x[(2 * p) * idim + k], x[(2 * p + 1) * idim + k]);
    }
    __syncthreads();

    // Layer 1 (weights straight from gmem; only idim k's)
    u64 acc[8];
    {
        u64 bp = dup2(b1[t]);
        #pragma unroll
        for (int p = 0; p < 8; ++p) acc[p] = bp;
        #pragma unroll 4
        for (int k = 0; k < idim; ++k) {
            u64 w2 = dup2(W1[k * HID + t]);
            ulonglong2 x01 = *(const ulonglong2*)&xp[k][0];
            ulonglong2 x23 = *(const ulonglong2*)&xp[k][2];
            ulonglong2 x45 = *(const ulonglong2*)&xp[k][4];
            ulonglong2 x67 = *(const ulonglong2*)&xp[k][6];
            acc[0] = ffma2_(x01.x, w2, acc[0]);
            acc[1] = ffma2_(x01.y, w2, acc[1]);
            acc[2] = ffma2_(x23.x, w2, acc[2]);
            acc[3] = ffma2_(x23.y, w2, acc[3]);
            acc[4] = ffma2_(x45.x, w2, acc[4]);
            acc[5] = ffma2_(x45.y, w2, acc[5]);
            acc[6] = ffma2_(x67.x, w2, acc[6]);
            acc[7] = ffma2_(x67.y, w2, acc[7]);
        }
        #pragma unroll
        for (int p = 0; p < 8; ++p) hT[t][p] = relu2_(acc[p]);
    }
    __syncthreads();

    // 8 chunks: 0-3 = W2, 4-7 = Ws. Double-buffered cp.async pipeline.
    #pragma unroll
    for (int p = 0; p < 8; ++p) acc[p] = 0ull;
    #pragma unroll 1
    for (int c = 0; c < 8; ++c) {
        cp_wait0();
        __syncthreads();          // chunk c visible; all warps done with buf of c-1
        if (c < 7) {
            const float* nsrc = (c + 1 < 4) ? (W2 + (c + 1) * CHK * HID)
                                            : (Ws + (c + 1 - 4) * CHK * HID);
            unsigned s = (unsigned)__cvta_generic_to_shared(&Wbuf[(c + 1) & 1][0]);
            #pragma unroll
            for (int i = 0; i < 8; ++i) {
                int seg = i * 128 + t;
                cp_async16(s + seg * 16, nsrc + seg * 4);
            }
            cp_commit();
        }
        const float* wb = Wbuf[c & 1];
        #pragma unroll 4
        for (int kk = 0; kk < CHK; ++kk) {
            int k = (c & 3) * CHK + kk;
            u64 w2 = dup2(wb[kk * HID + t]);
            ulonglong2 x01 = *(const ulonglong2*)&hT[k][0];
            ulonglong2 x23 = *(const ulonglong2*)&hT[k][2];
            ulonglong2 x45 = *(const ulonglong2*)&hT[k][4];
            ulonglong2 x67 = *(const ulonglong2*)&hT[k][6];
            acc[0] = ffma2_(x01.x, w2, acc[0]);
            acc[1] = ffma2_(x01.y, w2, acc[1]);
            acc[2] = ffma2_(x23.x, w2, acc[2]);
            acc[3] = ffma2_(x23.y, w2, acc[3]);
            acc[4] = ffma2_(x45.x, w2, acc[4]);
            acc[5] = ffma2_(x45.y, w2, acc[5]);
            acc[6] = ffma2_(x67.x, w2, acc[6]);
            acc[7] = ffma2_(x67.y, w2, acc[7]);
        }
        if (c == 3) {             // end of layer 2: relu(acc + b2) -> hT
            u64 b2d = dup2(b2[t]);
            __syncthreads();      // all warps done reading hT for chunks 0-3
            #pragma unroll
            for (int p = 0; p < 8; ++p) {
                hT[t][p] = relu2_(fadd2_(acc[p], b2d));
                acc[p] = 0ull;
            }
            __syncthreads();
        }
    }

    // Epilogue: acc = Ws·h2 (+ bs1 for agents), write packed rows.
    u64 bsd = agent ? dup2(bs1[t]) : 0ull;
    #pragma unroll
    for (int p = 0; p < 8; ++p) {
        u64 v = agent ? fadd2_(acc[p], bsd) : acc[p];
        float2 f = unpack2(v);
        int row = rbase + 2 * p;
        outp[row * HID + t]       = f.x;
        outp[(row + 1) * HID + t] = f.y;
    }
}

// ---------------------------------------------------------------------------
// Kernel 2: pairwise scores, f32x2 packed over (h, h+1).
// Block tile 64a x 32r, 128 threads, 4a x 4r register tile per thread
// (a = ty+16i, r = tx+8jj). Two h-pairs fetched per LDS.128.
// Pitch 68 floats (16B-aligned rows; conflict-free). Grid 512.
// ---------------------------------------------------------------------------
__global__ __launch_bounds__(128, 6) void pair_kernel(
    const float* __restrict__ Ws2, const float* __restrict__ bs2,
    float* __restrict__ out)
{
    __shared__ __align__(16) float As[64 * 68];   // [a][h_local], 17.4KB
    __shared__ __align__(16) float Rs[32 * 68];   // [r][h_local],  8.7KB
    __shared__ __align__(16) u64   wsp[64];       // Ws2 as natural h-pairs

    int t  = threadIdx.x;
    int tx = t & 7;          // r = tx + 8*jj
    int ty = t >> 3;         // a = ty + 16*i   (ty 0..15)
    int a0 = blockIdx.y * 64;
    int r0 = blockIdx.x * 32;

    if (t < 64) wsp[t] = ((const u64*)Ws2)[t];

    u64 acc[4][4];
    #pragma unroll
    for (int i = 0; i < 4; ++i)
        #pragma unroll
        for (int jj = 0; jj < 4; ++jj) acc[i][jj] = 0ull;

    const u64* As64 = (const u64*)As;   // pitch 34 u64
    const u64* Rs64 = (const u64*)Rs;

    for (int c = 0; c < 2; ++c) {
        int hb = 64 * c;
        __syncthreads();   // previous chunk's reads done (and wsp on c==0)

        #pragma unroll
        for (int it = 0; it < 8; ++it) {
            int idx = t + 128 * it;
            int row = idx >> 4, c4 = idx & 15;
            *(float4*)&As[row * 68 + 4 * c4] =
                *(const float4*)&g_PA[(size_t)(a0 + row) * HID + hb + 4 * c4];
        }
        #pragma unroll
        for (int it = 0; it < 4; ++it) {
            int idx = t + 128 * it;
            int row = idx >> 4, c4 = idx & 15;
            *(float4*)&Rs[row * 68 + 4 * c4] =
                *(const float4*)&g_PR[(size_t)(r0 + row) * HID + hb + 4 * c4];
        }
        __syncthreads();

        #pragma unroll 2
        for (int hd = 0; hd < 16; ++hd) {   // 2 packed h-pairs per iter
            int hp = 2 * hd;
            ulonglong2 wv = *(const ulonglong2*)&wsp[32 * c + hp];
            ulonglong2 av[4], rv[4];
            #pragma unroll
            for (int i = 0; i < 4; ++i)
                av[i] = *(const ulonglong2*)&As64[(ty + 16 * i) * 34 + hp];
            #pragma unroll
            for (int jj = 0; jj < 4; ++jj)
                rv[jj] = *(const ulonglong2*)&Rs64[(tx + 8 * jj) * 34 + hp];
            #pragma unroll
            for (int i = 0; i < 4; ++i)
                #pragma unroll
                for (int jj = 0; jj < 4; ++jj) {
                    acc[i][jj] = addrelufma(acc[i][jj], av[i].x, rv[jj].x, wv.x);
                    acc[i][jj] = addrelufma(acc[i][jj], av[i].y, rv[jj].y, wv.y);
                }
        }
    }

    float b = *bs2;
    #pragma unroll
    for (int i = 0; i < 4; ++i) {
        int a = a0 + ty + 16 * i;
        #pragma unroll
        for (int jj = 0; jj < 4; ++jj) {
            float2 p = unpack2(acc[i][jj]);
            out[(size_t)a * NR + r0 + tx + 8 * jj] = (p.x + p.y) + b;
        }
    }
}

// ---------------------------------------------------------------------------
extern "C" void kernel_launch(void* const* d_in, const int* in_sizes, int n_in,
                              void* d_out, int out_size)
{
    const float* xa  = (const float*)d_in[0];
    const float* xr  = (const float*)d_in[1];
    const float* Wa1 = (const float*)d_in[2];
    const float* ba1 = (const float*)d_in[3];
    const float* Wa2 = (const float*)d_in[4];
    const float* ba2 = (const float*)d_in[5];
    const float* Wr1 = (const float*)d_in[6];
    const float* br1 = (const float*)d_in[7];
    const float* Wr2 = (const float*)d_in[8];
    const float* br2 = (const float*)d_in[9];
    const float* Ws1 = (const float*)d_in[10];
    const float* bs1 = (const float*)d_in[11];
    const float* Ws2 = (const float*)d_in[12];
    const float* bs2 = (const float*)d_in[13];
    float* out = (float*)d_out;

    embed_kernel<<<128, 128>>>(xa, xr, Wa1, ba1, Wa2, ba2,
                               Wr1, br1, Wr2, br2, Ws1, bs1);
    pair_kernel<<<dim3(NR / 32, NA / 64), 128>>>(Ws2, bs2, out);
}